// round 1
// baseline (speedup 1.0000x reference)
#include <cuda_runtime.h>
#include <cuda_bf16.h>

// MoE combine: out[token_idx[r]] += gates[r] * expert_hidden[r]
// Strategy: bucket rows by token (CSR-lite, fixed CAP + exact overflow list),
// then gather per token -> single coalesced write of out. No output atomics,
// no output zero-init.

#define MAX_TOKENS 16384
#define MAX_ROWS   32768
#define CAP        32

__device__ int g_count[MAX_TOKENS];
__device__ int g_bucket[MAX_TOKENS * CAP];
__device__ int g_ovf_count;
__device__ int g_ovf_rows[MAX_ROWS];

__global__ void zero_counts_kernel(int num_tokens) {
    int i = blockIdx.x * blockDim.x + threadIdx.x;
    if (i < num_tokens) g_count[i] = 0;
    if (i == 0) g_ovf_count = 0;
}

__global__ void bucket_kernel(const int* __restrict__ token_idx, int num_rows) {
    int r = blockIdx.x * blockDim.x + threadIdx.x;
    if (r >= num_rows) return;
    int t = token_idx[r];
    int p = atomicAdd(&g_count[t], 1);
    if (p < CAP) {
        g_bucket[t * CAP + p] = r;
    } else {
        int q = atomicAdd(&g_ovf_count, 1);
        g_ovf_rows[q] = r;
    }
}

// One block per token. blockDim.x = 512, hidden4 = hidden/4 (float4 columns).
__global__ void combine_kernel(const float* __restrict__ expert_hidden,
                               const int*   __restrict__ token_idx,
                               const float* __restrict__ gates,
                               float* __restrict__ out,
                               int hidden4) {
    const int t = blockIdx.x;
    __shared__ int   s_rows[CAP];
    __shared__ float s_gates[CAP];
    __shared__ int   s_n;

    if (threadIdx.x == 0) s_n = g_count[t];
    __syncthreads();
    const int n = s_n;
    const int m = (n < CAP) ? n : CAP;

    // Stage row ids + gates once
    if (threadIdx.x < m) {
        int r = g_bucket[t * CAP + threadIdx.x];
        s_rows[threadIdx.x]  = r;
        s_gates[threadIdx.x] = gates[r];
    }
    __syncthreads();

    const float4* eh4  = reinterpret_cast<const float4*>(expert_hidden);
    float4*       out4 = reinterpret_cast<float4*>(out);

    for (int base = threadIdx.x; base < hidden4; base += blockDim.x) {
        float4 acc = make_float4(0.f, 0.f, 0.f, 0.f);
        #pragma unroll 4
        for (int i = 0; i < m; i++) {
            const int   r = s_rows[i];
            const float g = s_gates[i];
            float4 v = eh4[(long long)r * hidden4 + base];
            acc.x += g * v.x;
            acc.y += g * v.y;
            acc.z += g * v.z;
            acc.w += g * v.w;
        }
        // Exact overflow handling (normally dead code: g_ovf_count == 0)
        if (n > CAP) {
            int q = g_ovf_count;
            for (int j = 0; j < q; j++) {
                int r = g_ovf_rows[j];
                if (token_idx[r] == t) {
                    float g = gates[r];
                    float4 v = eh4[(long long)r * hidden4 + base];
                    acc.x += g * v.x;
                    acc.y += g * v.y;
                    acc.z += g * v.z;
                    acc.w += g * v.w;
                }
            }
        }
        out4[(long long)t * hidden4 + base] = acc;
    }
}

extern "C" void kernel_launch(void* const* d_in, const int* in_sizes, int n_in,
                              void* d_out, int out_size) {
    const float* expert_hidden = (const float*)d_in[0];
    const int*   token_idx     = (const int*)d_in[1];
    const float* gates         = (const float*)d_in[2];
    float*       out           = (float*)d_out;

    const int num_rows   = in_sizes[1];               // 32768
    const int hidden     = in_sizes[0] / num_rows;    // 4096
    const int num_tokens = out_size / hidden;         // 16384
    const int hidden4    = hidden / 4;

    zero_counts_kernel<<<(num_tokens + 255) / 256, 256>>>(num_tokens);
    bucket_kernel<<<(num_rows + 255) / 256, 256>>>(token_idx, num_rows);
    combine_kernel<<<num_tokens, 512>>>(expert_hidden, token_idx, gates, out, hidden4);
}

// round 2
// speedup vs baseline: 1.2814x; 1.2814x over previous
#include <cuda_runtime.h>
#include <cuda_bf16.h>

// MoE combine: out[token_idx[r]] += gates[r] * expert_hidden[r]
// CSR-lite buckets (CAP + exact overflow list) -> per-token gather ->
// single coalesced write. R2: MLP-4 combine (256 thr x 4 float4 cols),
// streaming cache hints.

#define MAX_TOKENS 16384
#define MAX_ROWS   32768
#define CAP        32
#define CTHREADS   256
#define VPT        4   // float4 columns per thread

__device__ int g_count[MAX_TOKENS];
__device__ int g_bucket[MAX_TOKENS * CAP];
__device__ int g_ovf_count;
__device__ int g_ovf_rows[MAX_ROWS];

__global__ void zero_counts_kernel(int num_tokens) {
    int i = blockIdx.x * blockDim.x + threadIdx.x;
    if (i < num_tokens) g_count[i] = 0;
    if (i == 0) g_ovf_count = 0;
}

__global__ void bucket_kernel(const int* __restrict__ token_idx, int num_rows) {
    int r = blockIdx.x * blockDim.x + threadIdx.x;
    if (r >= num_rows) return;
    int t = token_idx[r];
    int p = atomicAdd(&g_count[t], 1);
    if (p < CAP) {
        g_bucket[t * CAP + p] = r;
    } else {
        int q = atomicAdd(&g_ovf_count, 1);
        g_ovf_rows[q] = r;
    }
}

// One block per token. Each thread owns VPT float4 columns, strided by
// blockDim so all loads/stores stay fully coalesced. Per bucket row we
// issue VPT independent loads back-to-back -> MLP >= VPT.
__global__ __launch_bounds__(CTHREADS)
void combine_kernel(const float* __restrict__ expert_hidden,
                    const int*   __restrict__ token_idx,
                    const float* __restrict__ gates,
                    float* __restrict__ out,
                    int hidden4) {
    const int t = blockIdx.x;
    __shared__ int   s_rows[CAP];
    __shared__ float s_gates[CAP];
    __shared__ int   s_n;

    if (threadIdx.x == 0) s_n = g_count[t];
    __syncthreads();
    const int n = s_n;
    const int m = (n < CAP) ? n : CAP;

    if (threadIdx.x < m) {
        int r = g_bucket[t * CAP + threadIdx.x];
        s_rows[threadIdx.x]  = r;
        s_gates[threadIdx.x] = gates[r];
    }
    __syncthreads();

    const float4* eh4  = reinterpret_cast<const float4*>(expert_hidden);
    float4*       out4 = reinterpret_cast<float4*>(out);

    // Outer tile of VPT*CTHREADS float4 columns (one iteration for hidden=4096).
    for (int tile = 0; tile < hidden4; tile += VPT * CTHREADS) {
        int col[VPT];
        bool ok[VPT];
        #pragma unroll
        for (int j = 0; j < VPT; j++) {
            col[j] = tile + threadIdx.x + j * CTHREADS;
            ok[j]  = col[j] < hidden4;
        }

        float4 acc[VPT];
        #pragma unroll
        for (int j = 0; j < VPT; j++) acc[j] = make_float4(0.f, 0.f, 0.f, 0.f);

        for (int i = 0; i < m; i++) {
            const long long rb = (long long)s_rows[i] * hidden4;
            const float g = s_gates[i];
            float4 v[VPT];
            #pragma unroll
            for (int j = 0; j < VPT; j++)
                if (ok[j]) v[j] = __ldcs(&eh4[rb + col[j]]);
            #pragma unroll
            for (int j = 0; j < VPT; j++) {
                if (ok[j]) {
                    acc[j].x += g * v[j].x;
                    acc[j].y += g * v[j].y;
                    acc[j].z += g * v[j].z;
                    acc[j].w += g * v[j].w;
                }
            }
        }

        // Exact overflow handling (normally dead: bucket overflow ~ never)
        if (n > CAP) {
            int q = g_ovf_count;
            for (int jj = 0; jj < q; jj++) {
                int r = g_ovf_rows[jj];
                if (token_idx[r] == t) {
                    float g = gates[r];
                    long long rb = (long long)r * hidden4;
                    #pragma unroll
                    for (int j = 0; j < VPT; j++) {
                        if (ok[j]) {
                            float4 v = eh4[rb + col[j]];
                            acc[j].x += g * v.x;
                            acc[j].y += g * v.y;
                            acc[j].z += g * v.z;
                            acc[j].w += g * v.w;
                        }
                    }
                }
            }
        }

        const long long ob = (long long)t * hidden4;
        #pragma unroll
        for (int j = 0; j < VPT; j++)
            if (ok[j]) __stcs(&out4[ob + col[j]], acc[j]);
    }
}

extern "C" void kernel_launch(void* const* d_in, const int* in_sizes, int n_in,
                              void* d_out, int out_size) {
    const float* expert_hidden = (const float*)d_in[0];
    const int*   token_idx     = (const int*)d_in[1];
    const float* gates         = (const float*)d_in[2];
    float*       out           = (float*)d_out;

    const int num_rows   = in_sizes[1];               // 32768
    const int hidden     = in_sizes[0] / num_rows;    // 4096
    const int num_tokens = out_size / hidden;         // 16384
    const int hidden4    = hidden / 4;

    zero_counts_kernel<<<(num_tokens + 255) / 256, 256>>>(num_tokens);
    bucket_kernel<<<(num_rows + 255) / 256, 256>>>(token_idx, num_rows);
    combine_kernel<<<num_tokens, CTHREADS>>>(expert_hidden, token_idx, gates, out, hidden4);
}